// round 15
// baseline (speedup 1.0000x reference)
#include <cuda_runtime.h>
#include <cuda_bf16.h>
#include <cstdint>
#include <math.h>

#define Bn    64
#define Cc    128
#define HWn   3136
#define MTOT  (Bn*HWn)
#define NCOV  148
#define NNEW  32
#define EPSV  1e-5f

// ---------------- device scratch ----------------
__device__ float g_pS1[NCOV*Cc*Cc];
__device__ float g_psum[NCOV*Cc];
__device__ float g_Sigma[Cc*Cc];
__device__ float g_M32[Cc*Cc];
__device__ float g_bias[Cc];
__device__ __align__(4) __nv_bfloat16 g_Mh[Cc*Cc];
__device__ __align__(4) __nv_bfloat16 g_Ml[Cc*Cc];
__device__ unsigned g_bar_ctr = 0;

// ---------------- helpers ----------------
__device__ __forceinline__ uint32_t smem_u32(const void* p) {
    uint32_t a;
    asm("{ .reg .u64 t; cvta.to.shared.u64 t, %1; cvt.u32.u64 %0, t; }" : "=r"(a) : "l"(p));
    return a;
}
#define SWZ(x) ((x) ^ (((x) >> 3) & 0x70))

#define LDM_X4(r0,r1,r2,r3,addr) \
    asm volatile("ldmatrix.sync.aligned.m8n8.x4.shared.b16 {%0,%1,%2,%3}, [%4];" \
        : "=r"(r0),"=r"(r1),"=r"(r2),"=r"(r3) : "r"(addr))
#define LDM_X4T(r0,r1,r2,r3,addr) \
    asm volatile("ldmatrix.sync.aligned.m8n8.x4.trans.shared.b16 {%0,%1,%2,%3}, [%4];" \
        : "=r"(r0),"=r"(r1),"=r"(r2),"=r"(r3) : "r"(addr))
// NOTE: no volatile — register-pure, let ptxas schedule/pipeline
#define MMA16816(d,a0,a1,a2,a3,b0,b1) \
    asm("mma.sync.aligned.m16n8k16.row.col.f32.bf16.bf16.f32 " \
        "{%0,%1,%2,%3}, {%4,%5,%6,%7}, {%8,%9}, {%0,%1,%2,%3};" \
        : "+f"((d)[0]),"+f"((d)[1]),"+f"((d)[2]),"+f"((d)[3]) \
        : "r"(a0),"r"(a1),"r"(a2),"r"(a3),"r"(b0),"r"(b1))

__device__ __forceinline__ uint32_t packbf(__nv_bfloat16 a, __nv_bfloat16 b) {
    return ((uint32_t)__bfloat16_as_ushort(b) << 16) | (uint32_t)__bfloat16_as_ushort(a);
}

// 512-thread tile loaders: 4 float4 per thread per 128x64 tile
__device__ __forceinline__ void load_raw(const float* __restrict__ x, int ti, float4* raw) {
    const int b = ti / 49;
    const int hw0 = (ti - b * 49) * 64;
    const int t = threadIdx.x;
#pragma unroll
    for (int i = 0; i < 4; i++) {
        const int q = i * 512 + t;
        const int r = q >> 4, c4 = q & 15;
        raw[i] = *(const float4*)(x + ((size_t)(b * Cc + r)) * HWn + hw0 + c4 * 4);
    }
}

// cov: hi-only convert (round-nearest), plus exact fp32 channel sums
__device__ __forceinline__ void convert_hi(const float4* raw, char* hb, float* sacc) {
    const int t = threadIdx.x;
#pragma unroll
    for (int i = 0; i < 4; i++) {
        const int q = i * 512 + t;
        const int r = q >> 4, c4 = q & 15;
        const float4 v = raw[i];
        sacc[i] += (v.x + v.y) + (v.z + v.w);
        uint2 ph;
        asm("cvt.rn.bf16x2.f32 %0, %1, %2;" : "=r"(ph.x) : "f"(v.y), "f"(v.x));
        asm("cvt.rn.bf16x2.f32 %0, %1, %2;" : "=r"(ph.y) : "f"(v.w), "f"(v.z));
        *(uint2*)(hb + SWZ((uint32_t)(r * 128 + c4 * 8))) = ph;
    }
}

// transform: round-nearest hi/lo split
__device__ __forceinline__ void convert_store2(const float4* raw, char* hb, char* lb) {
    const int t = threadIdx.x;
#pragma unroll
    for (int i = 0; i < 4; i++) {
        const int q = i * 512 + t;
        const int r = q >> 4, c4 = q & 15;
        const float4 v = raw[i];
        __nv_bfloat16 h0 = __float2bfloat16(v.x), h1 = __float2bfloat16(v.y);
        __nv_bfloat16 h2 = __float2bfloat16(v.z), h3 = __float2bfloat16(v.w);
        uint2 ph; ph.x = packbf(h0, h1); ph.y = packbf(h2, h3);
        __nv_bfloat16 l0 = __float2bfloat16(v.x - __bfloat162float(h0));
        __nv_bfloat16 l1 = __float2bfloat16(v.y - __bfloat162float(h1));
        __nv_bfloat16 l2 = __float2bfloat16(v.z - __bfloat162float(h2));
        __nv_bfloat16 l3 = __float2bfloat16(v.w - __bfloat162float(h3));
        uint2 pl; pl.x = packbf(l0, l1); pl.y = packbf(l2, l3);
        const uint32_t off = SWZ((uint32_t)(r * 128 + c4 * 8));
        *(uint2*)(hb + off) = ph;
        *(uint2*)(lb + off) = pl;
    }
}

// =========================================================================
// k_cov (512 threads): S1 = Xh*Xh^T (hi-only SYRK), proven round-14 version.
// =========================================================================
__global__ __launch_bounds__(512, 1) void k_cov(const float* __restrict__ x) {
    extern __shared__ __align__(128) char dyn[];
    const int t = threadIdx.x, p = blockIdx.x;
    const int w = t >> 5, l = t & 31;
    const int rbase = (w & 3) * 32;
    const int cb8   = (w >> 2) * 4;

    const int t0  = p * 21 + min(p, 28);
    const int cnt = 21 + (p < 28 ? 1 : 0);

    float sacc[4] = {0.f, 0.f, 0.f, 0.f};
    float d[2][4][4];
#pragma unroll
    for (int b2 = 0; b2 < 2; b2++)
#pragma unroll
        for (int j = 0; j < 4; j++)
#pragma unroll
            for (int q = 0; q < 4; q++) d[b2][j][q] = 0.f;

    float4 raw[4];
    load_raw(x, t0, raw);
    convert_hi(raw, dyn, sacc);
    __syncthreads();

    for (int i = 0; i < cnt; i++) {
        const uint32_t hba = smem_u32(dyn + (i & 1) * 16384);
        const bool pf = (i + 1 < cnt);

        if (pf) load_raw(x, t0 + i + 1, raw);

#pragma unroll
        for (int ks = 0; ks < 4; ks++) {
            uint32_t a[2][4];
#pragma unroll
            for (int blk = 0; blk < 2; blk++) {
                const uint32_t ao = hba + SWZ((uint32_t)((rbase + blk*16 + (l & 15))*128
                                              + ks*32 + (l >> 4)*16));
                LDM_X4(a[blk][0], a[blk][1], a[blk][2], a[blk][3], ao);
            }
#pragma unroll
            for (int jbp = 0; jbp < 2; jbp++) {
                uint32_t b0, b1, b2, b3;
                const uint32_t bo = hba + SWZ((uint32_t)(((cb8 + jbp*2 + (l >> 4))*8
                                              + (l & 7))*128 + ks*32 + ((l >> 3) & 1)*16));
                LDM_X4(b0, b1, b2, b3, bo);
                MMA16816(d[0][jbp*2],   a[0][0],a[0][1],a[0][2],a[0][3], b0, b1);
                MMA16816(d[1][jbp*2],   a[1][0],a[1][1],a[1][2],a[1][3], b0, b1);
                MMA16816(d[0][jbp*2+1], a[0][0],a[0][1],a[0][2],a[0][3], b2, b3);
                MMA16816(d[1][jbp*2+1], a[1][0],a[1][1],a[1][2],a[1][3], b2, b3);
            }
        }

        if (pf) convert_hi(raw, dyn + ((i + 1) & 1) * 16384, sacc);
        __syncthreads();
    }

    float* dst = g_pS1 + (size_t)p * 16384;
#pragma unroll
    for (int blk = 0; blk < 2; blk++) {
#pragma unroll
        for (int jb = 0; jb < 4; jb++) {
            const int r0 = rbase + blk*16 + (l >> 2);
            const int c  = cb8*8 + jb*8 + (l & 3)*2;
            *(float2*)&dst[r0*128 + c]       = make_float2(d[blk][jb][0], d[blk][jb][1]);
            *(float2*)&dst[(r0 + 8)*128 + c] = make_float2(d[blk][jb][2], d[blk][jb][3]);
        }
    }

#pragma unroll
    for (int i = 0; i < 4; i++) {
#pragma unroll
        for (int off = 8; off > 0; off >>= 1)
            sacc[i] += __shfl_down_sync(0xffffffffu, sacc[i], off, 16);
    }
    if ((t & 15) == 0) {
#pragma unroll
        for (int i = 0; i < 4; i++) g_psum[p * Cc + i * 32 + (t >> 4)] = sacc[i];
    }
}

// =========================================================================
// k_newton v2: phase 1 (Sigma assembly) distributed over 32 CTAs + ONE grid
// barrier; then CTA 0 alone runs 13 matmuls as split-bf16 HMMA in smem.
// Matrices in smem as bf16 hi/lo, 128 rows x 256B, XOR-16B swizzle.
// dyn smem: Yh@0 Yl@32K Zh@64K Zl@96K Th@128K Tl@160K (192KB)
// =========================================================================
__device__ __forceinline__ void nstore(char* Dh, char* Dl, int r, int c, float a, float b) {
    __nv_bfloat16 h0 = __float2bfloat16(a), h1 = __float2bfloat16(b);
    const uint32_t ph = packbf(h0, h1);
    const uint32_t pl = packbf(__float2bfloat16(a - __bfloat162float(h0)),
                               __float2bfloat16(b - __bfloat162float(h1)));
    const uint32_t off = (uint32_t)r * 256 + (((uint32_t)c * 2) ^ (uint32_t)((r & 7) << 4));
    *(uint32_t*)(Dh + off) = ph;
    *(uint32_t*)(Dl + off) = pl;
}

// C = Ah*Bh + Ah*Bl + Al*Bh over 128^3; 512 threads, warp grid 4x4, tile 32x32.
// mode 0: D = 3I - C (smem)   mode 1: D = 0.5*C (smem)
// mode 2: M = scale*C -> g_Mh/g_Ml/g_M32 (gmem)
__device__ __forceinline__ void mmCTA(const char* Ah, const char* Al,
                                      const char* Bh, const char* Bl,
                                      char* Dh, char* Dl, int mode, float scale) {
    const int t = threadIdx.x;
    const int w = t >> 5, l = t & 31;
    const int rbase = (w & 3) * 32;
    const int cb = w >> 2;
    const uint32_t aha = smem_u32(Ah), ala = smem_u32(Al);
    const uint32_t bha = smem_u32(Bh), bla = smem_u32(Bl);

    float d[2][4][4];
#pragma unroll
    for (int b2 = 0; b2 < 2; b2++)
#pragma unroll
        for (int j = 0; j < 4; j++)
#pragma unroll
            for (int q = 0; q < 4; q++) d[b2][j][q] = 0.f;

#pragma unroll
    for (int ks = 0; ks < 8; ks++) {
        uint32_t ah[2][4], al2[2][4];
#pragma unroll
        for (int blk = 0; blk < 2; blk++) {
            const int arow = rbase + blk * 16 + (l & 15);
            const uint32_t ao = (uint32_t)arow * 256
                + ((uint32_t)(ks * 32 + (l >> 4) * 16) ^ (uint32_t)((arow & 7) << 4));
            LDM_X4(ah[blk][0], ah[blk][1], ah[blk][2], ah[blk][3], aha + ao);
            LDM_X4(al2[blk][0], al2[blk][1], al2[blk][2], al2[blk][3], ala + ao);
        }
        const int brow = ks * 16 + (l & 15);
#pragma unroll
        for (int nbp = 0; nbp < 2; nbp++) {
            const uint32_t bo = (uint32_t)brow * 256
                + ((uint32_t)(cb * 64 + nbp * 32 + (l >> 4) * 16) ^ (uint32_t)((brow & 7) << 4));
            uint32_t bh0, bh1, bh2, bh3, bl0, bl1, bl2, bl3;
            LDM_X4T(bh0, bh1, bh2, bh3, bha + bo);
            LDM_X4T(bl0, bl1, bl2, bl3, bla + bo);
#pragma unroll
            for (int blk = 0; blk < 2; blk++) {
                MMA16816(d[blk][nbp*2],   ah[blk][0],ah[blk][1],ah[blk][2],ah[blk][3], bh0, bh1);
                MMA16816(d[blk][nbp*2+1], ah[blk][0],ah[blk][1],ah[blk][2],ah[blk][3], bh2, bh3);
                MMA16816(d[blk][nbp*2],   ah[blk][0],ah[blk][1],ah[blk][2],ah[blk][3], bl0, bl1);
                MMA16816(d[blk][nbp*2+1], ah[blk][0],ah[blk][1],ah[blk][2],ah[blk][3], bl2, bl3);
                MMA16816(d[blk][nbp*2],   al2[blk][0],al2[blk][1],al2[blk][2],al2[blk][3], bh0, bh1);
                MMA16816(d[blk][nbp*2+1], al2[blk][0],al2[blk][1],al2[blk][2],al2[blk][3], bh2, bh3);
            }
        }
    }

    __syncthreads();   // all operand reads done before in-place writeback
#pragma unroll
    for (int blk = 0; blk < 2; blk++) {
#pragma unroll
        for (int jb = 0; jb < 4; jb++) {
            const int r0 = rbase + blk * 16 + (l >> 2);
            const int c  = cb * 32 + jb * 8 + (l & 3) * 2;
            float v00 = d[blk][jb][0], v01 = d[blk][jb][1];
            float v10 = d[blk][jb][2], v11 = d[blk][jb][3];
            if (mode == 0) {
                v00 = ((r0 == c)     ? 3.f : 0.f) - v00;
                v01 = ((r0 == c + 1) ? 3.f : 0.f) - v01;
                v10 = ((r0 + 8 == c)     ? 3.f : 0.f) - v10;
                v11 = ((r0 + 8 == c + 1) ? 3.f : 0.f) - v11;
            } else if (mode == 1) {
                v00 *= 0.5f; v01 *= 0.5f; v10 *= 0.5f; v11 *= 0.5f;
            } else {
                v00 *= scale; v01 *= scale; v10 *= scale; v11 *= scale;
            }
            if (mode == 2) {
                __nv_bfloat16 h0 = __float2bfloat16(v00), h1 = __float2bfloat16(v01);
                __nv_bfloat16 h2 = __float2bfloat16(v10), h3 = __float2bfloat16(v11);
                ((uint32_t*)g_Mh)[(r0 * 128 + c) >> 1]       = packbf(h0, h1);
                ((uint32_t*)g_Mh)[((r0 + 8) * 128 + c) >> 1] = packbf(h2, h3);
                ((uint32_t*)g_Ml)[(r0 * 128 + c) >> 1] =
                    packbf(__float2bfloat16(v00 - __bfloat162float(h0)),
                           __float2bfloat16(v01 - __bfloat162float(h1)));
                ((uint32_t*)g_Ml)[((r0 + 8) * 128 + c) >> 1] =
                    packbf(__float2bfloat16(v10 - __bfloat162float(h2)),
                           __float2bfloat16(v11 - __bfloat162float(h3)));
                *(float2*)&g_M32[r0 * 128 + c]       = make_float2(v00, v01);
                *(float2*)&g_M32[(r0 + 8) * 128 + c] = make_float2(v10, v11);
            } else {
                nstore(Dh, Dl, r0, c, v00, v01);
                nstore(Dh, Dl, r0 + 8, c, v10, v11);
            }
        }
    }
    __syncthreads();
}

__global__ __launch_bounds__(512) void k_newton(const float* __restrict__ rot) {
    extern __shared__ __align__(128) char nsm[];
    __shared__ float mn[128];
    __shared__ float red[128];
    const int t = threadIdx.x, p = blockIdx.x;

    if (t < 128) {
        float s = 0.f;
        for (int q = 0; q < NCOV; q++) s += __ldcg(&g_psum[q * Cc + t]);
        mn[t] = s * (1.f / (float)MTOT);
    }
    __syncthreads();
    // distributed Sigma assembly: CTA p owns elements [p*512, p*512+512)
    if (t < 256) {
        const int e0 = p * 512 + t * 2;
        const int i = e0 >> 7, j = e0 & 127;
        float s0 = 0.f, s1 = 0.f;
        for (int q = 0; q < NCOV; q++) {
            const float2 a = __ldcg((const float2*)(g_pS1 + (size_t)q * 16384 + e0));
            s0 += a.x; s1 += a.y;
        }
        float v0 = s0 * (1.f / (float)MTOT) - mn[i] * mn[j];
        float v1 = s1 * (1.f / (float)MTOT) - mn[i] * mn[j + 1];
        if (i == j)     v0 += EPSV;
        if (i == j + 1) v1 += EPSV;
        *(float2*)&g_Sigma[e0] = make_float2(v0, v1);
    }
    __threadfence();
    __syncthreads();
    if (t == 0) atomicAdd(&g_bar_ctr, 1u);
    if (p != 0) return;

    // ---- CTA 0 only from here ----
    if (t == 0) { while (atomicAdd(&g_bar_ctr, 0u) < 32u) { } }
    __syncthreads();

    char* Yh = nsm;           char* Yl = nsm + 32768;
    char* Zh = nsm + 65536;   char* Zl = nsm + 98304;
    char* Th = nsm + 131072;  char* Tl = nsm + 163840;

    // trace -> rTr
    if (t < 128) red[t] = __ldcg(&g_Sigma[t * 129]);
    __syncthreads();
    for (int s = 64; s > 0; s >>= 1) {
        if (t < s) red[t] += red[t + s];
        __syncthreads();
    }
    const float rTr = 1.f / red[0];
    const float sc1 = sqrtf(rTr);

    // elementwise init: Y0 = rTr*Sigma; T0 = 3I - Y0; Z1 = 0.5*T0
    for (int pr = t; pr < 8192; pr += 512) {
        const int r = pr >> 6;
        const int c = (pr & 63) * 2;
        const float2 s = __ldcg((const float2*)&g_Sigma[r * 128 + c]);
        const float y0 = rTr * s.x, y1 = rTr * s.y;
        const float t0 = ((r == c)     ? 3.f : 0.f) - y0;
        const float t1 = ((r == c + 1) ? 3.f : 0.f) - y1;
        nstore(Yh, Yl, r, c, y0, y1);
        nstore(Th, Tl, r, c, t0, t1);
        nstore(Zh, Zl, r, c, 0.5f * t0, 0.5f * t1);
    }
    __syncthreads();

    // Y1 = 0.5*Y0*T0
    mmCTA(Yh, Yl, Th, Tl, Yh, Yl, 1, 0.f);
    // 3 coupled iterations
    for (int k = 0; k < 3; k++) {
        mmCTA(Zh, Zl, Yh, Yl, Th, Tl, 0, 0.f);   // T = 3I - Z*Y
        mmCTA(Yh, Yl, Th, Tl, Yh, Yl, 1, 0.f);   // Y = 0.5*Y*T
        mmCTA(Th, Tl, Zh, Zl, Zh, Zl, 1, 0.f);   // Z = 0.5*T*Z
    }
    // T = 3I - Z4*Y4 ; Z5 = 0.5*T*Z4
    mmCTA(Zh, Zl, Yh, Yl, Th, Tl, 0, 0.f);
    mmCTA(Th, Tl, Zh, Zl, Zh, Zl, 1, 0.f);

    // load rot into Y buffers (hi/lo split)
    for (int pr = t; pr < 8192; pr += 512) {
        const int r = pr >> 6;
        const int c = (pr & 63) * 2;
        const float2 rv = __ldcg((const float2*)&rot[r * 128 + c]);
        nstore(Yh, Yl, r, c, rv.x, rv.y);
    }
    __syncthreads();
    // M = sc1 * rot * Z5 -> g_Mh/g_Ml/g_M32
    mmCTA(Yh, Yl, Zh, Zl, 0, 0, 2, sc1);

    // bias = M @ mean
    if (t < 128) {
        float s = 0.f;
        const float* Mrow = g_M32 + t * 128;
        for (int c = 0; c < 128; c++) s += Mrow[c] * mn[c];
        g_bias[t] = s;
    }
    __syncthreads();
    if (t == 0) {
        g_bar_ctr = 0u;       // reset for graph replay
        __threadfence();
    }
}

// =========================================================================
// k_transform (512 threads): D = Mh*Xh + Mh*Xl + Ml*Xh - bias.
// M frags in regs; double-buffered X tiles; MMAs interleaved across the two
// accumulators (2 independent chains), no volatile on MMA.
// dyn smem: Mstage@0 (32KB), tiles@32K (64KB)  total 96KB
// =========================================================================
__global__ __launch_bounds__(512, 1) void k_transform(const float* __restrict__ x,
                                                      float* __restrict__ out) {
    extern __shared__ __align__(128) char dyn[];
    char* Ms   = dyn;
    char* tile = dyn + 32768;
    const int t = threadIdx.x, p = blockIdx.x;
    const int w = t >> 5, l = t & 31;
    const int rwarp = (w & 7) * 16;
    const int cbase = (w >> 3) * 32;

    // hoist M fragments
    uint32_t ah[8][4], al[8][4];
    const uint32_t msa = smem_u32(Ms);
    const int arow = rwarp + (l & 15);
#pragma unroll
    for (int pass = 0; pass < 2; pass++) {
        const uint32_t* src = (const uint32_t*)(pass ? g_Ml : g_Mh);
        for (int idx = t; idx < 8192; idx += 512) {
            const int row = idx >> 6;
            const uint32_t kb = (uint32_t)(idx & 63) * 4;
            *(uint32_t*)(Ms + (uint32_t)row * 256 + (kb ^ (uint32_t)((row & 7) << 4))) = src[idx];
        }
        __syncthreads();
#pragma unroll
        for (int ks = 0; ks < 8; ks++) {
            const uint32_t akb = (uint32_t)(ks*32 + (l >> 4)*16);
            const uint32_t aoff = (uint32_t)arow * 256 + (akb ^ (uint32_t)((arow & 7) << 4));
            if (pass == 0) { LDM_X4(ah[ks][0], ah[ks][1], ah[ks][2], ah[ks][3], msa + aoff); }
            else           { LDM_X4(al[ks][0], al[ks][1], al[ks][2], al[ks][3], msa + aoff); }
        }
        __syncthreads();
    }

    const int r0 = rwarp + (l >> 2);
    const float bi0 = g_bias[r0], bi1 = g_bias[r0 + 8];

    const int t0  = p * 21 + min(p, 28);
    const int cnt = 21 + (p < 28 ? 1 : 0);
    float4 raw[4];

    load_raw(x, t0, raw);
    convert_store2(raw, tile, tile + 16384);
    __syncthreads();

    for (int i = 0; i < cnt; i++) {
        const uint32_t hba = smem_u32(tile + (i & 1) * 32768);
        const uint32_t lba = hba + 16384u;

        if (i + 1 < cnt) load_raw(x, t0 + i + 1, raw);

        float d[4][4];
#pragma unroll
        for (int nb = 0; nb < 4; nb++)
#pragma unroll
            for (int q = 0; q < 4; q++) d[nb][q] = 0.f;

#pragma unroll
        for (int ks = 0; ks < 8; ks++) {
#pragma unroll
            for (int nbp = 0; nbp < 2; nbp++) {
                const uint32_t boff = SWZ((uint32_t)((ks*16 + (l & 15))*128
                                          + cbase*2 + nbp*32 + (l >> 4)*16));
                uint32_t bh0, bh1, bh2, bh3, bl0, bl1, bl2, bl3;
                LDM_X4T(bh0, bh1, bh2, bh3, hba + boff);
                LDM_X4T(bl0, bl1, bl2, bl3, lba + boff);
                // interleaved: two independent accumulator chains
                MMA16816(d[nbp*2],   ah[ks][0],ah[ks][1],ah[ks][2],ah[ks][3], bh0, bh1);
                MMA16816(d[nbp*2+1], ah[ks][0],ah[ks][1],ah[ks][2],ah[ks][3], bh2, bh3);
                MMA16816(d[nbp*2],   ah[ks][0],ah[ks][1],ah[ks][2],ah[ks][3], bl0, bl1);
                MMA16816(d[nbp*2+1], ah[ks][0],ah[ks][1],ah[ks][2],ah[ks][3], bl2, bl3);
                MMA16816(d[nbp*2],   al[ks][0],al[ks][1],al[ks][2],al[ks][3], bh0, bh1);
                MMA16816(d[nbp*2+1], al[ks][0],al[ks][1],al[ks][2],al[ks][3], bh2, bh3);
            }
        }

        const int tj = t0 + i;
        const int b = tj / 49;
        const int hw0 = (tj - b * 49) * 64;
        float* ob = out + (size_t)b * Cc * HWn + hw0;
#pragma unroll
        for (int nb = 0; nb < 4; nb++) {
            const int n = cbase + nb*8 + (l & 3)*2;
            *(float2*)(ob + (size_t)r0*HWn + n)     = make_float2(d[nb][0]-bi0, d[nb][1]-bi0);
            *(float2*)(ob + (size_t)(r0+8)*HWn + n) = make_float2(d[nb][2]-bi1, d[nb][3]-bi1);
        }

        if (i + 1 < cnt) {
            char* nh = tile + ((i + 1) & 1) * 32768;
            convert_store2(raw, nh, nh + 16384);
        }
        __syncthreads();
    }
}

// =========================================================================
extern "C" void kernel_launch(void* const* d_in, const int* in_sizes, int n_in,
                              void* d_out, int out_size) {
    const float* x   = (const float*)d_in[0];
    const float* rot = (const float*)d_in[1];
    float* out = (float*)d_out;
    (void)in_sizes; (void)n_in; (void)out_size;

    cudaFuncSetAttribute(k_cov,       cudaFuncAttributeMaxDynamicSharedMemorySize, 32768);
    cudaFuncSetAttribute(k_newton,    cudaFuncAttributeMaxDynamicSharedMemorySize, 196608);
    cudaFuncSetAttribute(k_transform, cudaFuncAttributeMaxDynamicSharedMemorySize, 98304);

    k_cov<<<NCOV, 512, 32768>>>(x);
    k_newton<<<NNEW, 512, 196608>>>(rot);
    k_transform<<<NCOV, 512, 98304>>>(x, out);
}

// round 16
// speedup vs baseline: 1.1105x; 1.1105x over previous
#include <cuda_runtime.h>
#include <cuda_bf16.h>
#include <cstdint>
#include <math.h>

#define Bn    64
#define Cc    128
#define HWn   3136
#define MTOT  (Bn*HWn)
#define NCOV  148
#define NNEW  32
#define EPSV  1e-5f

// ---------------- device scratch ----------------
__device__ float g_pS1[NCOV*Cc*Cc];
__device__ float g_psum[NCOV*Cc];
__device__ float g_bufs[5][Cc*Cc];      // 0=Z 1=Y0 2=T 3=Sigma 4=M/Y1...
__device__ float g_bias[Cc];
__device__ __align__(4) __nv_bfloat16 g_Mh[Cc*Cc];
__device__ __align__(4) __nv_bfloat16 g_Ml[Cc*Cc];
__device__ unsigned g_bar_ctr  = 0;
__device__ unsigned g_exit_ctr = 0;

// ---------------- helpers ----------------
__device__ __forceinline__ uint32_t smem_u32(const void* p) {
    uint32_t a;
    asm("{ .reg .u64 t; cvta.to.shared.u64 t, %1; cvt.u32.u64 %0, t; }" : "=r"(a) : "l"(p));
    return a;
}
#define SWZ(x) ((x) ^ (((x) >> 3) & 0x70))

#define LDM_X4(r0,r1,r2,r3,addr) \
    asm volatile("ldmatrix.sync.aligned.m8n8.x4.shared.b16 {%0,%1,%2,%3}, [%4];" \
        : "=r"(r0),"=r"(r1),"=r"(r2),"=r"(r3) : "r"(addr))
#define LDM_X4T(r0,r1,r2,r3,addr) \
    asm volatile("ldmatrix.sync.aligned.m8n8.x4.trans.shared.b16 {%0,%1,%2,%3}, [%4];" \
        : "=r"(r0),"=r"(r1),"=r"(r2),"=r"(r3) : "r"(addr))
// no volatile: register-pure, let ptxas schedule/pipeline
#define MMA16816(d,a0,a1,a2,a3,b0,b1) \
    asm("mma.sync.aligned.m16n8k16.row.col.f32.bf16.bf16.f32 " \
        "{%0,%1,%2,%3}, {%4,%5,%6,%7}, {%8,%9}, {%0,%1,%2,%3};" \
        : "+f"((d)[0]),"+f"((d)[1]),"+f"((d)[2]),"+f"((d)[3]) \
        : "r"(a0),"r"(a1),"r"(a2),"r"(a3),"r"(b0),"r"(b1))

__device__ __forceinline__ uint32_t packbf(__nv_bfloat16 a, __nv_bfloat16 b) {
    return ((uint32_t)__bfloat16_as_ushort(b) << 16) | (uint32_t)__bfloat16_as_ushort(a);
}

// 512-thread tile loaders: 4 float4 per thread per 128x64 tile
__device__ __forceinline__ void load_raw(const float* __restrict__ x, int ti, float4* raw) {
    const int b = ti / 49;
    const int hw0 = (ti - b * 49) * 64;
    const int t = threadIdx.x;
#pragma unroll
    for (int i = 0; i < 4; i++) {
        const int q = i * 512 + t;
        const int r = q >> 4, c4 = q & 15;
        raw[i] = *(const float4*)(x + ((size_t)(b * Cc + r)) * HWn + hw0 + c4 * 4);
    }
}

// cov: hi-only convert (round-nearest), plus exact fp32 channel sums
__device__ __forceinline__ void convert_hi(const float4* raw, char* hb, float* sacc) {
    const int t = threadIdx.x;
#pragma unroll
    for (int i = 0; i < 4; i++) {
        const int q = i * 512 + t;
        const int r = q >> 4, c4 = q & 15;
        const float4 v = raw[i];
        sacc[i] += (v.x + v.y) + (v.z + v.w);
        uint2 ph;
        asm("cvt.rn.bf16x2.f32 %0, %1, %2;" : "=r"(ph.x) : "f"(v.y), "f"(v.x));
        asm("cvt.rn.bf16x2.f32 %0, %1, %2;" : "=r"(ph.y) : "f"(v.w), "f"(v.z));
        *(uint2*)(hb + SWZ((uint32_t)(r * 128 + c4 * 8))) = ph;
    }
}

// transform: round-nearest hi/lo split
__device__ __forceinline__ void convert_store2(const float4* raw, char* hb, char* lb) {
    const int t = threadIdx.x;
#pragma unroll
    for (int i = 0; i < 4; i++) {
        const int q = i * 512 + t;
        const int r = q >> 4, c4 = q & 15;
        const float4 v = raw[i];
        __nv_bfloat16 h0 = __float2bfloat16(v.x), h1 = __float2bfloat16(v.y);
        __nv_bfloat16 h2 = __float2bfloat16(v.z), h3 = __float2bfloat16(v.w);
        uint2 ph; ph.x = packbf(h0, h1); ph.y = packbf(h2, h3);
        __nv_bfloat16 l0 = __float2bfloat16(v.x - __bfloat162float(h0));
        __nv_bfloat16 l1 = __float2bfloat16(v.y - __bfloat162float(h1));
        __nv_bfloat16 l2 = __float2bfloat16(v.z - __bfloat162float(h2));
        __nv_bfloat16 l3 = __float2bfloat16(v.w - __bfloat162float(h3));
        uint2 pl; pl.x = packbf(l0, l1); pl.y = packbf(l2, l3);
        const uint32_t off = SWZ((uint32_t)(r * 128 + c4 * 8));
        *(uint2*)(hb + off) = ph;
        *(uint2*)(lb + off) = pl;
    }
}

// =========================================================================
// k_cov (512 threads): S1 = Xh*Xh^T (hi-only SYRK) — proven round-14.
// dyn smem: hb0@0, hb1@16K (32KB)
// =========================================================================
__global__ __launch_bounds__(512, 1) void k_cov(const float* __restrict__ x) {
    extern __shared__ __align__(128) char dyn[];
    const int t = threadIdx.x, p = blockIdx.x;
    const int w = t >> 5, l = t & 31;
    const int rbase = (w & 3) * 32;
    const int cb8   = (w >> 2) * 4;

    const int t0  = p * 21 + min(p, 28);
    const int cnt = 21 + (p < 28 ? 1 : 0);

    float sacc[4] = {0.f, 0.f, 0.f, 0.f};
    float d[2][4][4];
#pragma unroll
    for (int b2 = 0; b2 < 2; b2++)
#pragma unroll
        for (int j = 0; j < 4; j++)
#pragma unroll
            for (int q = 0; q < 4; q++) d[b2][j][q] = 0.f;

    float4 raw[4];
    load_raw(x, t0, raw);
    convert_hi(raw, dyn, sacc);
    __syncthreads();

    for (int i = 0; i < cnt; i++) {
        const uint32_t hba = smem_u32(dyn + (i & 1) * 16384);
        const bool pf = (i + 1 < cnt);

        if (pf) load_raw(x, t0 + i + 1, raw);

#pragma unroll
        for (int ks = 0; ks < 4; ks++) {
            uint32_t a[2][4];
#pragma unroll
            for (int blk = 0; blk < 2; blk++) {
                const uint32_t ao = hba + SWZ((uint32_t)((rbase + blk*16 + (l & 15))*128
                                              + ks*32 + (l >> 4)*16));
                LDM_X4(a[blk][0], a[blk][1], a[blk][2], a[blk][3], ao);
            }
#pragma unroll
            for (int jbp = 0; jbp < 2; jbp++) {
                uint32_t b0, b1, b2, b3;
                const uint32_t bo = hba + SWZ((uint32_t)(((cb8 + jbp*2 + (l >> 4))*8
                                              + (l & 7))*128 + ks*32 + ((l >> 3) & 1)*16));
                LDM_X4(b0, b1, b2, b3, bo);
                MMA16816(d[0][jbp*2],   a[0][0],a[0][1],a[0][2],a[0][3], b0, b1);
                MMA16816(d[1][jbp*2],   a[1][0],a[1][1],a[1][2],a[1][3], b0, b1);
                MMA16816(d[0][jbp*2+1], a[0][0],a[0][1],a[0][2],a[0][3], b2, b3);
                MMA16816(d[1][jbp*2+1], a[1][0],a[1][1],a[1][2],a[1][3], b2, b3);
            }
        }

        if (pf) convert_hi(raw, dyn + ((i + 1) & 1) * 16384, sacc);
        __syncthreads();
    }

    float* dst = g_pS1 + (size_t)p * 16384;
#pragma unroll
    for (int blk = 0; blk < 2; blk++) {
#pragma unroll
        for (int jb = 0; jb < 4; jb++) {
            const int r0 = rbase + blk*16 + (l >> 2);
            const int c  = cb8*8 + jb*8 + (l & 3)*2;
            *(float2*)&dst[r0*128 + c]       = make_float2(d[blk][jb][0], d[blk][jb][1]);
            *(float2*)&dst[(r0 + 8)*128 + c] = make_float2(d[blk][jb][2], d[blk][jb][3]);
        }
    }

#pragma unroll
    for (int i = 0; i < 4; i++) {
#pragma unroll
        for (int off = 8; off > 0; off >>= 1)
            sacc[i] += __shfl_down_sync(0xffffffffu, sacc[i], off, 16);
    }
    if ((t & 15) == 0) {
#pragma unroll
        for (int i = 0; i < 4; i++) g_psum[p * Cc + i * 32 + (t >> 4)] = sacc[i];
    }
}

// =========================================================================
// k_newton: proven round-14 version. Persistent 32 CTAs, coupled
// Newton-Schulz, 12 grid barriers, fp32 distributed matmuls.
// =========================================================================
__device__ __forceinline__ void gbar(unsigned phn) {
    __threadfence();
    __syncthreads();
    if (threadIdx.x == 0) {
        atomicAdd(&g_bar_ctr, 1u);
        const unsigned tgt = 32u * phn;
        while (atomicAdd(&g_bar_ctr, 0u) < tgt) { }
    }
    __syncthreads();
}

__device__ __forceinline__ void mm4(int r0, const float* __restrict__ A,
        const float* __restrict__ B, float* __restrict__ C,
        int mode, float c0, float* Bs, float* As) {
    const int t = threadIdx.x;
    __syncthreads();
    ((float2*)As)[t] = __ldcg((const float2*)(A + r0 * 128) + t);
    const int c = t & 127;
    const int rr = (t >> 7) * 2;
    float a0 = 0.f, a1 = 0.f;
    for (int kb = 0; kb < 4; kb++) {
        __syncthreads();
#pragma unroll
        for (int i = 0; i < 4; i++)
            ((float4*)Bs)[i * 256 + t] = __ldcg((const float4*)(B + kb * 4096) + i * 256 + t);
        __syncthreads();
#pragma unroll 8
        for (int k = 0; k < 32; k++) {
            const float bv = Bs[k * 128 + c];
            a0 += As[rr * 128 + kb * 32 + k] * bv;
            a1 += As[(rr + 1) * 128 + kb * 32 + k] * bv;
        }
    }
    const int i0 = r0 + rr;
    const int e0 = i0 * 128 + c;
    if (mode == 4)      { C[e0] = 0.5f * a0; C[e0 + 128] = 0.5f * a1; }
    else if (mode == 3) { C[e0]       = ((i0 == c)     ? 3.f : 0.f) - a0;
                          C[e0 + 128] = ((i0 + 1 == c) ? 3.f : 0.f) - a1; }
    else                { C[e0] = c0 * a0; C[e0 + 128] = c0 * a1; }
}

__global__ __launch_bounds__(256) void k_newton(const float* __restrict__ rot) {
    __shared__ float Bs[32 * 128];
    __shared__ float As[512];
    __shared__ float mn[128];
    __shared__ float red[128];
    __shared__ float bred[256];
    const int t = threadIdx.x, p = blockIdx.x;

    if (t < 128) {
        float s = 0.f;
        for (int q = 0; q < NCOV; q++) s += __ldcg(&g_psum[q * Cc + t]);
        mn[t] = s * (1.f / (float)MTOT);
    }
    __syncthreads();
    // fused: Sigma = sum(S1)/m - mu mu^T + eps I  (own 512 elements)
    {
        const int e0 = p * 512 + t * 2;
        const int i = e0 >> 7, j = e0 & 127;
        float s0 = 0.f, s1 = 0.f;
        for (int q = 0; q < NCOV; q++) {
            const float2 a = __ldcg((const float2*)(g_pS1 + (size_t)q * 16384 + e0));
            s0 += a.x; s1 += a.y;
        }
        float v0 = s0 * (1.f / (float)MTOT) - mn[i] * mn[j];
        float v1 = s1 * (1.f / (float)MTOT) - mn[i] * mn[j + 1];
        if (i == j)     v0 += EPSV;
        if (i == j + 1) v1 += EPSV;
        *(float2*)&g_bufs[3][e0] = make_float2(v0, v1);
    }
    gbar(1);
    // trace; Y0 = rTr*Sigma -> bufs[1]; T0 = 3I - Y0 -> bufs[2]; Z1 = 0.5*T0 -> bufs[0]
    if (t < 128) red[t] = __ldcg(&g_bufs[3][t * 129]);
    __syncthreads();
    for (int s = 64; s > 0; s >>= 1) {
        if (t < s) red[t] += red[t + s];
        __syncthreads();
    }
    const float rTr = 1.f / red[0];
    const float sc1 = sqrtf(rTr);
#pragma unroll
    for (int u = 0; u < 2; u++) {
        const int e = p * 512 + t * 2 + u;
        const float y0 = rTr * g_bufs[3][e];
        const float t0v = ((e >> 7) == (e & 127) ? 3.f : 0.f) - y0;
        g_bufs[1][e] = y0;
        g_bufs[2][e] = t0v;
        g_bufs[0][e] = 0.5f * t0v;
    }
    gbar(2);
    // Y1 = 0.5*Y0*T0 -> bufs[3]
    mm4(4 * p, g_bufs[1], g_bufs[2], g_bufs[3], 4, 0.f, Bs, As);
    gbar(3);

    const int Zc[4] = {0, 4, 0, 4};
    const int Yc[4] = {3, 1, 3, 1};
    unsigned bar = 3;
    for (int k = 0; k < 3; k++) {
        mm4(4 * p, g_bufs[Zc[k]], g_bufs[Yc[k]], g_bufs[2], 3, 0.f, Bs, As);
        gbar(++bar);
        if (p < 16) {
            mm4(8 * p,     g_bufs[Yc[k]], g_bufs[2], g_bufs[Yc[k + 1]], 4, 0.f, Bs, As);
            mm4(8 * p + 4, g_bufs[Yc[k]], g_bufs[2], g_bufs[Yc[k + 1]], 4, 0.f, Bs, As);
        } else {
            const int q = p - 16;
            mm4(8 * q,     g_bufs[2], g_bufs[Zc[k]], g_bufs[Zc[k + 1]], 4, 0.f, Bs, As);
            mm4(8 * q + 4, g_bufs[2], g_bufs[Zc[k]], g_bufs[Zc[k + 1]], 4, 0.f, Bs, As);
        }
        gbar(++bar);
    }
    // T = 3I - Z4*Y4 (Z4@4, Y4@1); Z5 = 0.5*T*Z4 -> bufs[0]; M = sc1*rot*Z5 -> bufs[4]
    mm4(4 * p, g_bufs[4], g_bufs[1], g_bufs[2], 3, 0.f, Bs, As); gbar(++bar);   // 10
    mm4(4 * p, g_bufs[2], g_bufs[4], g_bufs[0], 4, 0.f, Bs, As); gbar(++bar);   // 11
    mm4(4 * p, rot,       g_bufs[0], g_bufs[4], 2, sc1, Bs, As); gbar(++bar);   // 12

    // epilogue: bias (own 4 rows) + M bf16 split
    {
        const int r = p * 4 + (t >> 6);
        const int cl = t & 63;
        bred[t] = __ldcg(&g_bufs[4][r * 128 + cl]) * mn[cl]
                + __ldcg(&g_bufs[4][r * 128 + 64 + cl]) * mn[64 + cl];
        __syncthreads();
        for (int s = 32; s > 0; s >>= 1) {
            if ((t & 63) < s) bred[t] += bred[t + s];
            __syncthreads();
        }
        if ((t & 63) == 0) g_bias[r] = bred[t];
    }
    {
        const float2 mv = __ldcg((const float2*)&g_bufs[4][p * 512 + t * 2]);
        __nv_bfloat16 h0 = __float2bfloat16(mv.x), h1 = __float2bfloat16(mv.y);
        __nv_bfloat16 l0 = __float2bfloat16(mv.x - __bfloat162float(h0));
        __nv_bfloat16 l1 = __float2bfloat16(mv.y - __bfloat162float(h1));
        ((uint32_t*)g_Mh)[p * 256 + t] = packbf(h0, h1);
        ((uint32_t*)g_Ml)[p * 256 + t] = packbf(l0, l1);
    }
    __syncthreads();
    if (t == 0) {
        __threadfence();
        const unsigned v = atomicAdd(&g_exit_ctr, 1u);
        if (v == 31u) { g_bar_ctr = 0u; g_exit_ctr = 0u; __threadfence(); }
    }
}

// =========================================================================
// k_transform (512 threads): D = Mh*Xh + Mh*Xl + Ml*Xh - bias.
// M frags in regs; double-buffered X tiles; non-volatile MMAs interleaved
// across the two independent accumulator chains.
// dyn smem: Mstage@0 (32KB), tiles@32K (64KB)  total 96KB
// =========================================================================
__global__ __launch_bounds__(512, 1) void k_transform(const float* __restrict__ x,
                                                      float* __restrict__ out) {
    extern __shared__ __align__(128) char dyn[];
    char* Ms   = dyn;
    char* tile = dyn + 32768;
    const int t = threadIdx.x, p = blockIdx.x;
    const int w = t >> 5, l = t & 31;
    const int rwarp = (w & 7) * 16;
    const int cbase = (w >> 3) * 32;

    // hoist M fragments
    uint32_t ah[8][4], al[8][4];
    const uint32_t msa = smem_u32(Ms);
    const int arow = rwarp + (l & 15);
#pragma unroll
    for (int pass = 0; pass < 2; pass++) {
        const uint32_t* src = (const uint32_t*)(pass ? g_Ml : g_Mh);
        for (int idx = t; idx < 8192; idx += 512) {
            const int row = idx >> 6;
            const uint32_t kb = (uint32_t)(idx & 63) * 4;
            *(uint32_t*)(Ms + (uint32_t)row * 256 + (kb ^ (uint32_t)((row & 7) << 4))) = src[idx];
        }
        __syncthreads();
#pragma unroll
        for (int ks = 0; ks < 8; ks++) {
            const uint32_t akb = (uint32_t)(ks*32 + (l >> 4)*16);
            const uint32_t aoff = (uint32_t)arow * 256 + (akb ^ (uint32_t)((arow & 7) << 4));
            if (pass == 0) { LDM_X4(ah[ks][0], ah[ks][1], ah[ks][2], ah[ks][3], msa + aoff); }
            else           { LDM_X4(al[ks][0], al[ks][1], al[ks][2], al[ks][3], msa + aoff); }
        }
        __syncthreads();
    }

    const int r0 = rwarp + (l >> 2);
    const float bi0 = g_bias[r0], bi1 = g_bias[r0 + 8];

    const int t0  = p * 21 + min(p, 28);
    const int cnt = 21 + (p < 28 ? 1 : 0);
    float4 raw[4];

    load_raw(x, t0, raw);
    convert_store2(raw, tile, tile + 16384);
    __syncthreads();

    for (int i = 0; i < cnt; i++) {
        const uint32_t hba = smem_u32(tile + (i & 1) * 32768);
        const uint32_t lba = hba + 16384u;

        if (i + 1 < cnt) load_raw(x, t0 + i + 1, raw);

        float d[4][4];
#pragma unroll
        for (int nb = 0; nb < 4; nb++)
#pragma unroll
            for (int q = 0; q < 4; q++) d[nb][q] = 0.f;

#pragma unroll
        for (int ks = 0; ks < 8; ks++) {
#pragma unroll
            for (int nbp = 0; nbp < 2; nbp++) {
                const uint32_t boff = SWZ((uint32_t)((ks*16 + (l & 15))*128
                                          + cbase*2 + nbp*32 + (l >> 4)*16));
                uint32_t bh0, bh1, bh2, bh3, bl0, bl1, bl2, bl3;
                LDM_X4T(bh0, bh1, bh2, bh3, hba + boff);
                LDM_X4T(bl0, bl1, bl2, bl3, lba + boff);
                // interleaved: two independent accumulator chains
                MMA16816(d[nbp*2],   ah[ks][0],ah[ks][1],ah[ks][2],ah[ks][3], bh0, bh1);
                MMA16816(d[nbp*2+1], ah[ks][0],ah[ks][1],ah[ks][2],ah[ks][3], bh2, bh3);
                MMA16816(d[nbp*2],   ah[ks][0],ah[ks][1],ah[ks][2],ah[ks][3], bl0, bl1);
                MMA16816(d[nbp*2+1], ah[ks][0],ah[ks][1],ah[ks][2],ah[ks][3], bl2, bl3);
                MMA16816(d[nbp*2],   al[ks][0],al[ks][1],al[ks][2],al[ks][3], bh0, bh1);
                MMA16816(d[nbp*2+1], al[ks][0],al[ks][1],al[ks][2],al[ks][3], bh2, bh3);
            }
        }

        const int tj = t0 + i;
        const int b = tj / 49;
        const int hw0 = (tj - b * 49) * 64;
        float* ob = out + (size_t)b * Cc * HWn + hw0;
#pragma unroll
        for (int nb = 0; nb < 4; nb++) {
            const int n = cbase + nb*8 + (l & 3)*2;
            *(float2*)(ob + (size_t)r0*HWn + n)     = make_float2(d[nb][0]-bi0, d[nb][1]-bi0);
            *(float2*)(ob + (size_t)(r0+8)*HWn + n) = make_float2(d[nb][2]-bi1, d[nb][3]-bi1);
        }

        if (i + 1 < cnt) {
            char* nh = tile + ((i + 1) & 1) * 32768;
            convert_store2(raw, nh, nh + 16384);
        }
        __syncthreads();
    }
}

// =========================================================================
extern "C" void kernel_launch(void* const* d_in, const int* in_sizes, int n_in,
                              void* d_out, int out_size) {
    const float* x   = (const float*)d_in[0];
    const float* rot = (const float*)d_in[1];
    float* out = (float*)d_out;
    (void)in_sizes; (void)n_in; (void)out_size;

    cudaFuncSetAttribute(k_cov,       cudaFuncAttributeMaxDynamicSharedMemorySize, 32768);
    cudaFuncSetAttribute(k_transform, cudaFuncAttributeMaxDynamicSharedMemorySize, 98304);

    k_cov<<<NCOV, 512, 32768>>>(x);
    k_newton<<<NNEW, 256>>>(rot);
    k_transform<<<NCOV, 512, 98304>>>(x, out);
}

// round 17
// speedup vs baseline: 1.2207x; 1.0992x over previous
#include <cuda_runtime.h>
#include <cuda_bf16.h>
#include <cstdint>
#include <math.h>

#define Bn    64
#define Cc    128
#define HWn   3136
#define MTOT  (Bn*HWn)
#define NCOV  148
#define NNEW  32
#define EPSV  1e-5f

// ---------------- device scratch ----------------
__device__ float g_pS1[NCOV*Cc*Cc];
__device__ float g_psum[NCOV*Cc];
__device__ float g_bufs[5][Cc*Cc];      // 0=Z 1=Y0 2=T 3=Sigma 4=M/Y1...
__device__ float g_bias[Cc];
__device__ __align__(4) __nv_bfloat16 g_Mh[Cc*Cc];
__device__ __align__(4) __nv_bfloat16 g_Ml[Cc*Cc];
__device__ unsigned g_bar_ctr  = 0;
__device__ unsigned g_exit_ctr = 0;

// ---------------- helpers ----------------
__device__ __forceinline__ uint32_t smem_u32(const void* p) {
    uint32_t a;
    asm("{ .reg .u64 t; cvta.to.shared.u64 t, %1; cvt.u32.u64 %0, t; }" : "=r"(a) : "l"(p));
    return a;
}
#define SWZ(x) ((x) ^ (((x) >> 3) & 0x70))

#define LDM_X4(r0,r1,r2,r3,addr) \
    asm volatile("ldmatrix.sync.aligned.m8n8.x4.shared.b16 {%0,%1,%2,%3}, [%4];" \
        : "=r"(r0),"=r"(r1),"=r"(r2),"=r"(r3) : "r"(addr))
#define LDM_X4T(r0,r1,r2,r3,addr) \
    asm volatile("ldmatrix.sync.aligned.m8n8.x4.trans.shared.b16 {%0,%1,%2,%3}, [%4];" \
        : "=r"(r0),"=r"(r1),"=r"(r2),"=r"(r3) : "r"(addr))
// no volatile: register-pure, let ptxas schedule/pipeline
#define MMA16816(d,a0,a1,a2,a3,b0,b1) \
    asm("mma.sync.aligned.m16n8k16.row.col.f32.bf16.bf16.f32 " \
        "{%0,%1,%2,%3}, {%4,%5,%6,%7}, {%8,%9}, {%0,%1,%2,%3};" \
        : "+f"((d)[0]),"+f"((d)[1]),"+f"((d)[2]),"+f"((d)[3]) \
        : "r"(a0),"r"(a1),"r"(a2),"r"(a3),"r"(b0),"r"(b1))

__device__ __forceinline__ uint32_t packbf(__nv_bfloat16 a, __nv_bfloat16 b) {
    return ((uint32_t)__bfloat16_as_ushort(b) << 16) | (uint32_t)__bfloat16_as_ushort(a);
}

// 512-thread tile loaders: 4 float4 per thread per 128x64 tile
__device__ __forceinline__ void load_raw(const float* __restrict__ x, int ti, float4* raw) {
    const int b = ti / 49;
    const int hw0 = (ti - b * 49) * 64;
    const int t = threadIdx.x;
#pragma unroll
    for (int i = 0; i < 4; i++) {
        const int q = i * 512 + t;
        const int r = q >> 4, c4 = q & 15;
        raw[i] = *(const float4*)(x + ((size_t)(b * Cc + r)) * HWn + hw0 + c4 * 4);
    }
}

// cov: hi-only convert (round-nearest), plus exact fp32 channel sums
__device__ __forceinline__ void convert_hi(const float4* raw, char* hb, float* sacc) {
    const int t = threadIdx.x;
#pragma unroll
    for (int i = 0; i < 4; i++) {
        const int q = i * 512 + t;
        const int r = q >> 4, c4 = q & 15;
        const float4 v = raw[i];
        sacc[i] += (v.x + v.y) + (v.z + v.w);
        uint2 ph;
        asm("cvt.rn.bf16x2.f32 %0, %1, %2;" : "=r"(ph.x) : "f"(v.y), "f"(v.x));
        asm("cvt.rn.bf16x2.f32 %0, %1, %2;" : "=r"(ph.y) : "f"(v.w), "f"(v.z));
        *(uint2*)(hb + SWZ((uint32_t)(r * 128 + c4 * 8))) = ph;
    }
}

// transform: round-nearest hi/lo split
__device__ __forceinline__ void convert_store2(const float4* raw, char* hb, char* lb) {
    const int t = threadIdx.x;
#pragma unroll
    for (int i = 0; i < 4; i++) {
        const int q = i * 512 + t;
        const int r = q >> 4, c4 = q & 15;
        const float4 v = raw[i];
        __nv_bfloat16 h0 = __float2bfloat16(v.x), h1 = __float2bfloat16(v.y);
        __nv_bfloat16 h2 = __float2bfloat16(v.z), h3 = __float2bfloat16(v.w);
        uint2 ph; ph.x = packbf(h0, h1); ph.y = packbf(h2, h3);
        __nv_bfloat16 l0 = __float2bfloat16(v.x - __bfloat162float(h0));
        __nv_bfloat16 l1 = __float2bfloat16(v.y - __bfloat162float(h1));
        __nv_bfloat16 l2 = __float2bfloat16(v.z - __bfloat162float(h2));
        __nv_bfloat16 l3 = __float2bfloat16(v.w - __bfloat162float(h3));
        uint2 pl; pl.x = packbf(l0, l1); pl.y = packbf(l2, l3);
        const uint32_t off = SWZ((uint32_t)(r * 128 + c4 * 8));
        *(uint2*)(hb + off) = ph;
        *(uint2*)(lb + off) = pl;
    }
}

// =========================================================================
// k_cov (512 threads): S1 = Xh*Xh^T (hi-only SYRK) — proven round-14.
// dyn smem: hb0@0, hb1@16K (32KB)
// =========================================================================
__global__ __launch_bounds__(512, 1) void k_cov(const float* __restrict__ x) {
    extern __shared__ __align__(128) char dyn[];
    const int t = threadIdx.x, p = blockIdx.x;
    const int w = t >> 5, l = t & 31;
    const int rbase = (w & 3) * 32;
    const int cb8   = (w >> 2) * 4;

    const int t0  = p * 21 + min(p, 28);
    const int cnt = 21 + (p < 28 ? 1 : 0);

    float sacc[4] = {0.f, 0.f, 0.f, 0.f};
    float d[2][4][4];
#pragma unroll
    for (int b2 = 0; b2 < 2; b2++)
#pragma unroll
        for (int j = 0; j < 4; j++)
#pragma unroll
            for (int q = 0; q < 4; q++) d[b2][j][q] = 0.f;

    float4 raw[4];
    load_raw(x, t0, raw);
    convert_hi(raw, dyn, sacc);
    __syncthreads();

    for (int i = 0; i < cnt; i++) {
        const uint32_t hba = smem_u32(dyn + (i & 1) * 16384);
        const bool pf = (i + 1 < cnt);

        if (pf) load_raw(x, t0 + i + 1, raw);

#pragma unroll
        for (int ks = 0; ks < 4; ks++) {
            uint32_t a[2][4];
#pragma unroll
            for (int blk = 0; blk < 2; blk++) {
                const uint32_t ao = hba + SWZ((uint32_t)((rbase + blk*16 + (l & 15))*128
                                              + ks*32 + (l >> 4)*16));
                LDM_X4(a[blk][0], a[blk][1], a[blk][2], a[blk][3], ao);
            }
#pragma unroll
            for (int jbp = 0; jbp < 2; jbp++) {
                uint32_t b0, b1, b2, b3;
                const uint32_t bo = hba + SWZ((uint32_t)(((cb8 + jbp*2 + (l >> 4))*8
                                              + (l & 7))*128 + ks*32 + ((l >> 3) & 1)*16));
                LDM_X4(b0, b1, b2, b3, bo);
                MMA16816(d[0][jbp*2],   a[0][0],a[0][1],a[0][2],a[0][3], b0, b1);
                MMA16816(d[1][jbp*2],   a[1][0],a[1][1],a[1][2],a[1][3], b0, b1);
                MMA16816(d[0][jbp*2+1], a[0][0],a[0][1],a[0][2],a[0][3], b2, b3);
                MMA16816(d[1][jbp*2+1], a[1][0],a[1][1],a[1][2],a[1][3], b2, b3);
            }
        }

        if (pf) convert_hi(raw, dyn + ((i + 1) & 1) * 16384, sacc);
        __syncthreads();
    }

    float* dst = g_pS1 + (size_t)p * 16384;
#pragma unroll
    for (int blk = 0; blk < 2; blk++) {
#pragma unroll
        for (int jb = 0; jb < 4; jb++) {
            const int r0 = rbase + blk*16 + (l >> 2);
            const int c  = cb8*8 + jb*8 + (l & 3)*2;
            *(float2*)&dst[r0*128 + c]       = make_float2(d[blk][jb][0], d[blk][jb][1]);
            *(float2*)&dst[(r0 + 8)*128 + c] = make_float2(d[blk][jb][2], d[blk][jb][3]);
        }
    }

#pragma unroll
    for (int i = 0; i < 4; i++) {
#pragma unroll
        for (int off = 8; off > 0; off >>= 1)
            sacc[i] += __shfl_down_sync(0xffffffffu, sacc[i], off, 16);
    }
    if ((t & 15) == 0) {
#pragma unroll
        for (int i = 0; i < 4; i++) g_psum[p * Cc + i * 32 + (t >> 4)] = sacc[i];
    }
}

// =========================================================================
// k_newton: persistent 32 CTAs, coupled Newton-Schulz, 12 grid barriers.
// This round: ld.acquire poll in gbar; reg double-buffered B in mm4.
// =========================================================================
__device__ __forceinline__ void gbar(unsigned phn) {
    __threadfence();
    __syncthreads();
    if (threadIdx.x == 0) {
        atomicAdd(&g_bar_ctr, 1u);
        const unsigned tgt = 32u * phn;
        unsigned v;
        do {
            asm volatile("ld.global.acquire.gpu.u32 %0, [%1];" : "=r"(v) : "l"(&g_bar_ctr));
        } while (v < tgt);
    }
    __syncthreads();
}

__device__ __forceinline__ void mm4(int r0, const float* __restrict__ A,
        const float* __restrict__ B, float* __restrict__ C,
        int mode, float c0, float* Bs, float* As) {
    const int t = threadIdx.x;
    __syncthreads();
    ((float2*)As)[t] = __ldcg((const float2*)(A + r0 * 128) + t);
    // prefetch kb=0 chunk into regs
    float4 pre[4];
#pragma unroll
    for (int i = 0; i < 4; i++)
        pre[i] = __ldcg((const float4*)(B) + i * 256 + t);

    const int c = t & 127;
    const int rr = (t >> 7) * 2;
    float a0 = 0.f, a1 = 0.f;
    for (int kb = 0; kb < 4; kb++) {
        __syncthreads();
#pragma unroll
        for (int i = 0; i < 4; i++)
            ((float4*)Bs)[i * 256 + t] = pre[i];
        __syncthreads();
        if (kb < 3) {     // overlap next chunk's L2 latency with compute
#pragma unroll
            for (int i = 0; i < 4; i++)
                pre[i] = __ldcg((const float4*)(B + (kb + 1) * 4096) + i * 256 + t);
        }
#pragma unroll 8
        for (int k = 0; k < 32; k++) {
            const float bv = Bs[k * 128 + c];
            a0 += As[rr * 128 + kb * 32 + k] * bv;
            a1 += As[(rr + 1) * 128 + kb * 32 + k] * bv;
        }
    }
    const int i0 = r0 + rr;
    const int e0 = i0 * 128 + c;
    if (mode == 4)      { C[e0] = 0.5f * a0; C[e0 + 128] = 0.5f * a1; }
    else if (mode == 3) { C[e0]       = ((i0 == c)     ? 3.f : 0.f) - a0;
                          C[e0 + 128] = ((i0 + 1 == c) ? 3.f : 0.f) - a1; }
    else                { C[e0] = c0 * a0; C[e0 + 128] = c0 * a1; }
}

__global__ __launch_bounds__(256) void k_newton(const float* __restrict__ rot) {
    __shared__ float Bs[32 * 128];
    __shared__ float As[512];
    __shared__ float mn[128];
    __shared__ float red[128];
    __shared__ float bred[256];
    const int t = threadIdx.x, p = blockIdx.x;

    if (t < 128) {
        float s = 0.f;
        for (int q = 0; q < NCOV; q++) s += __ldcg(&g_psum[q * Cc + t]);
        mn[t] = s * (1.f / (float)MTOT);
    }
    __syncthreads();
    // fused: Sigma = sum(S1)/m - mu mu^T + eps I  (own 512 elements)
    {
        const int e0 = p * 512 + t * 2;
        const int i = e0 >> 7, j = e0 & 127;
        float s0 = 0.f, s1 = 0.f;
        for (int q = 0; q < NCOV; q++) {
            const float2 a = __ldcg((const float2*)(g_pS1 + (size_t)q * 16384 + e0));
            s0 += a.x; s1 += a.y;
        }
        float v0 = s0 * (1.f / (float)MTOT) - mn[i] * mn[j];
        float v1 = s1 * (1.f / (float)MTOT) - mn[i] * mn[j + 1];
        if (i == j)     v0 += EPSV;
        if (i == j + 1) v1 += EPSV;
        *(float2*)&g_bufs[3][e0] = make_float2(v0, v1);
    }
    gbar(1);
    // trace; Y0 = rTr*Sigma -> bufs[1]; T0 = 3I - Y0 -> bufs[2]; Z1 = 0.5*T0 -> bufs[0]
    if (t < 128) red[t] = __ldcg(&g_bufs[3][t * 129]);
    __syncthreads();
    for (int s = 64; s > 0; s >>= 1) {
        if (t < s) red[t] += red[t + s];
        __syncthreads();
    }
    const float rTr = 1.f / red[0];
    const float sc1 = sqrtf(rTr);
#pragma unroll
    for (int u = 0; u < 2; u++) {
        const int e = p * 512 + t * 2 + u;
        const float y0 = rTr * g_bufs[3][e];
        const float t0v = ((e >> 7) == (e & 127) ? 3.f : 0.f) - y0;
        g_bufs[1][e] = y0;
        g_bufs[2][e] = t0v;
        g_bufs[0][e] = 0.5f * t0v;
    }
    gbar(2);
    // Y1 = 0.5*Y0*T0 -> bufs[3]
    mm4(4 * p, g_bufs[1], g_bufs[2], g_bufs[3], 4, 0.f, Bs, As);
    gbar(3);

    const int Zc[4] = {0, 4, 0, 4};
    const int Yc[4] = {3, 1, 3, 1};
    unsigned bar = 3;
    for (int k = 0; k < 3; k++) {
        mm4(4 * p, g_bufs[Zc[k]], g_bufs[Yc[k]], g_bufs[2], 3, 0.f, Bs, As);
        gbar(++bar);
        if (p < 16) {
            mm4(8 * p,     g_bufs[Yc[k]], g_bufs[2], g_bufs[Yc[k + 1]], 4, 0.f, Bs, As);
            mm4(8 * p + 4, g_bufs[Yc[k]], g_bufs[2], g_bufs[Yc[k + 1]], 4, 0.f, Bs, As);
        } else {
            const int q = p - 16;
            mm4(8 * q,     g_bufs[2], g_bufs[Zc[k]], g_bufs[Zc[k + 1]], 4, 0.f, Bs, As);
            mm4(8 * q + 4, g_bufs[2], g_bufs[Zc[k]], g_bufs[Zc[k + 1]], 4, 0.f, Bs, As);
        }
        gbar(++bar);
    }
    // T = 3I - Z4*Y4 (Z4@4, Y4@1); Z5 = 0.5*T*Z4 -> bufs[0]; M = sc1*rot*Z5 -> bufs[4]
    mm4(4 * p, g_bufs[4], g_bufs[1], g_bufs[2], 3, 0.f, Bs, As); gbar(++bar);   // 10
    mm4(4 * p, g_bufs[2], g_bufs[4], g_bufs[0], 4, 0.f, Bs, As); gbar(++bar);   // 11
    mm4(4 * p, rot,       g_bufs[0], g_bufs[4], 2, sc1, Bs, As); gbar(++bar);   // 12

    // epilogue: bias (own 4 rows) + M bf16 split
    {
        const int r = p * 4 + (t >> 6);
        const int cl = t & 63;
        bred[t] = __ldcg(&g_bufs[4][r * 128 + cl]) * mn[cl]
                + __ldcg(&g_bufs[4][r * 128 + 64 + cl]) * mn[64 + cl];
        __syncthreads();
        for (int s = 32; s > 0; s >>= 1) {
            if ((t & 63) < s) bred[t] += bred[t + s];
            __syncthreads();
        }
        if ((t & 63) == 0) g_bias[r] = bred[t];
    }
    {
        const float2 mv = __ldcg((const float2*)&g_bufs[4][p * 512 + t * 2]);
        __nv_bfloat16 h0 = __float2bfloat16(mv.x), h1 = __float2bfloat16(mv.y);
        __nv_bfloat16 l0 = __float2bfloat16(mv.x - __bfloat162float(h0));
        __nv_bfloat16 l1 = __float2bfloat16(mv.y - __bfloat162float(h1));
        ((uint32_t*)g_Mh)[p * 256 + t] = packbf(h0, h1);
        ((uint32_t*)g_Ml)[p * 256 + t] = packbf(l0, l1);
    }
    __syncthreads();
    if (t == 0) {
        __threadfence();
        const unsigned v = atomicAdd(&g_exit_ctr, 1u);
        if (v == 31u) { g_bar_ctr = 0u; g_exit_ctr = 0u; __threadfence(); }
    }
}

// =========================================================================
// k_transform (512 threads): D = Mh*Xh + Mh*Xl + Ml*Xh - bias.
// Tile-0 raw prefetch issued BEFORE M staging (hides first DRAM latency).
// dyn smem: Mstage@0 (32KB), tiles@32K (64KB)  total 96KB
// =========================================================================
__global__ __launch_bounds__(512, 1) void k_transform(const float* __restrict__ x,
                                                      float* __restrict__ out) {
    extern __shared__ __align__(128) char dyn[];
    char* Ms   = dyn;
    char* tile = dyn + 32768;
    const int t = threadIdx.x, p = blockIdx.x;
    const int w = t >> 5, l = t & 31;
    const int rwarp = (w & 7) * 16;
    const int cbase = (w >> 3) * 32;

    const int t0  = p * 21 + min(p, 28);
    const int cnt = 21 + (p < 28 ? 1 : 0);

    // issue tile-0 loads first — independent of M staging
    float4 raw[4];
    load_raw(x, t0, raw);

    // hoist M fragments
    uint32_t ah[8][4], al[8][4];
    const uint32_t msa = smem_u32(Ms);
    const int arow = rwarp + (l & 15);
#pragma unroll
    for (int pass = 0; pass < 2; pass++) {
        const uint32_t* src = (const uint32_t*)(pass ? g_Ml : g_Mh);
        for (int idx = t; idx < 8192; idx += 512) {
            const int row = idx >> 6;
            const uint32_t kb = (uint32_t)(idx & 63) * 4;
            *(uint32_t*)(Ms + (uint32_t)row * 256 + (kb ^ (uint32_t)((row & 7) << 4))) = src[idx];
        }
        __syncthreads();
#pragma unroll
        for (int ks = 0; ks < 8; ks++) {
            const uint32_t akb = (uint32_t)(ks*32 + (l >> 4)*16);
            const uint32_t aoff = (uint32_t)arow * 256 + (akb ^ (uint32_t)((arow & 7) << 4));
            if (pass == 0) { LDM_X4(ah[ks][0], ah[ks][1], ah[ks][2], ah[ks][3], msa + aoff); }
            else           { LDM_X4(al[ks][0], al[ks][1], al[ks][2], al[ks][3], msa + aoff); }
        }
        __syncthreads();
    }

    const int r0 = rwarp + (l >> 2);
    const float bi0 = g_bias[r0], bi1 = g_bias[r0 + 8];

    convert_store2(raw, tile, tile + 16384);
    __syncthreads();

    for (int i = 0; i < cnt; i++) {
        const uint32_t hba = smem_u32(tile + (i & 1) * 32768);
        const uint32_t lba = hba + 16384u;

        if (i + 1 < cnt) load_raw(x, t0 + i + 1, raw);

        float d[4][4];
#pragma unroll
        for (int nb = 0; nb < 4; nb++)
#pragma unroll
            for (int q = 0; q < 4; q++) d[nb][q] = 0.f;

#pragma unroll
        for (int ks = 0; ks < 8; ks++) {
#pragma unroll
            for (int nbp = 0; nbp < 2; nbp++) {
                const uint32_t boff = SWZ((uint32_t)((ks*16 + (l & 15))*128
                                          + cbase*2 + nbp*32 + (l >> 4)*16));
                uint32_t bh0, bh1, bh2, bh3, bl0, bl1, bl2, bl3;
                LDM_X4T(bh0, bh1, bh2, bh3, hba + boff);
                LDM_X4T(bl0, bl1, bl2, bl3, lba + boff);
                MMA16816(d[nbp*2],   ah[ks][0],ah[ks][1],ah[ks][2],ah[ks][3], bh0, bh1);
                MMA16816(d[nbp*2+1], ah[ks][0],ah[ks][1],ah[ks][2],ah[ks][3], bh2, bh3);
                MMA16816(d[nbp*2],   ah[ks][0],ah[ks][1],ah[ks][2],ah[ks][3], bl0, bl1);
                MMA16816(d[nbp*2+1], ah[ks][0],ah[ks][1],ah[ks][2],ah[ks][3], bl2, bl3);
                MMA16816(d[nbp*2],   al[ks][0],al[ks][1],al[ks][2],al[ks][3], bh0, bh1);
                MMA16816(d[nbp*2+1], al[ks][0],al[ks][1],al[ks][2],al[ks][3], bh2, bh3);
            }
        }

        const int tj = t0 + i;
        const int b = tj / 49;
        const int hw0 = (tj - b * 49) * 64;
        float* ob = out + (size_t)b * Cc * HWn + hw0;
#pragma unroll
        for (int nb = 0; nb < 4; nb++) {
            const int n = cbase + nb*8 + (l & 3)*2;
            *(float2*)(ob + (size_t)r0*HWn + n)     = make_float2(d[nb][0]-bi0, d[nb][1]-bi0);
            *(float2*)(ob + (size_t)(r0+8)*HWn + n) = make_float2(d[nb][2]-bi1, d[nb][3]-bi1);
        }

        if (i + 1 < cnt) {
            char* nh = tile + ((i + 1) & 1) * 32768;
            convert_store2(raw, nh, nh + 16384);
        }
        __syncthreads();
    }
}

// =========================================================================
extern "C" void kernel_launch(void* const* d_in, const int* in_sizes, int n_in,
                              void* d_out, int out_size) {
    const float* x   = (const float*)d_in[0];
    const float* rot = (const float*)d_in[1];
    float* out = (float*)d_out;
    (void)in_sizes; (void)n_in; (void)out_size;

    cudaFuncSetAttribute(k_cov,       cudaFuncAttributeMaxDynamicSharedMemorySize, 32768);
    cudaFuncSetAttribute(k_transform, cudaFuncAttributeMaxDynamicSharedMemorySize, 98304);

    k_cov<<<NCOV, 512, 32768>>>(x);
    k_newton<<<NNEW, 256>>>(rot);
    k_transform<<<NCOV, 512, 98304>>>(x, out);
}